// round 15
// baseline (speedup 1.0000x reference)
#include <cuda_runtime.h>

// GRNN scan: B=512, T=8192, state dim 2.
//
// ONE kernel, 16 CTAs x 128 threads (4 warps), 32 batches per CTA.
// Barrier-staged pipeline (stage = 32 steps), double-buffered smem by parity.
// One warp per SMSP (smsp = wid%4), each serial chain on a private scheduler:
//   wid3 (riccati): lane0, batch-independent symmetric Riccati, (u,v) packed
//        f32x2 -> X ring.                                      [stage k]
//   wid2 (prep):    consumes dy staged by cp.async (issued 2 stages ahead
//        into a 3-slot smem ring -> zero exposed L2 latency);
//        w = X dy (packed), G' = I + dt(A - X C).              [stage k-1]
//   wid0 (scan):    serial chain, pure smem, lookahead-4:
//        store x; s = G'x + w; x = min(max(s, x-.1), x+.1).    [stage k-2]
//   wid1 (drain):   out = dt C x -> gmem, coalesced.           [stage k-3]
// Runtime specialization for C == I, D diagonal (true here); general
// fallback kept.

#define T_STEPS 8192
#define NBATCH  512
#define DTF     1e-3f
#define CLIPX   0.1f
#define STG     32
#define NSTG    (T_STEPS / STG)
#define LA      4

typedef unsigned long long ull;

struct Smem {
    ull    Xuv[2][STG];            // riccati -> prep: packed (x00, x11)
    float  Xr[2][STG];             // riccati -> prep: x01 (== x10 special)
    float  Xr2[2][STG];            // general path only: x10
    float4 G[2][STG];              // prep -> scan: G' = I + dt(A - X C)
    float2 w[2][STG][33];          // prep -> scan, [t][b], padded
    float2 o[2][STG][33];          // scan -> drain, [t][b], padded
    float2 dyraw[3][32][STG];      // cp.async ring, [slot][b][t]
};

__device__ __forceinline__ float clamp1(float v, float lo, float hi) {
    return fminf(fmaxf(v, lo), hi);
}
__device__ __forceinline__ ull fpack(float lo, float hi) {
    ull d; asm("mov.b64 %0, {%1, %2};" : "=l"(d) : "f"(lo), "f"(hi)); return d;
}
__device__ __forceinline__ void funpack(float& lo, float& hi, ull v) {
    asm("mov.b64 {%0, %1}, %2;" : "=f"(lo), "=f"(hi) : "l"(v));
}
__device__ __forceinline__ ull fma2(ull a, ull b, ull c) {
    ull d; asm("fma.rn.f32x2 %0, %1, %2, %3;" : "=l"(d) : "l"(a), "l"(b), "l"(c));
    return d;
}
__device__ __forceinline__ ull mul2(ull a, ull b) {
    ull d; asm("mul.rn.f32x2 %0, %1, %2;" : "=l"(d) : "l"(a), "l"(b)); return d;
}

// Issue one stage of dy as a cp.async group (32 x 8B per lane, coalesced).
__device__ __forceinline__ void issue_dy_stage(const float2* __restrict__ dy,
                                               Smem* sm, int s, int lane,
                                               int b0) {
    const int slot = s % 3;
    const size_t tb = (size_t)s * STG + lane;
    unsigned sa = (unsigned)__cvta_generic_to_shared(&sm->dyraw[slot][0][lane]);
#pragma unroll 8
    for (int b = 0; b < 32; ++b) {
        const float2* src = &dy[(size_t)(b0 + b) * T_STEPS + tb];
        asm volatile("cp.async.ca.shared.global [%0], [%1], 8;"
                     :: "r"(sa + (unsigned)(b * (STG * 8))), "l"(src));
    }
    asm volatile("cp.async.commit_group;" ::: "memory");
}

// ---------------------------------------------------------------------------
template <bool SPECIAL>
__device__ void cta_run(const float2* __restrict__ dy,
                        const float* __restrict__ A,
                        const float* __restrict__ C,
                        const float* __restrict__ D,
                        float2* __restrict__ outg,
                        Smem* sm, int wid, int lane, int b0) {
    const float a00 = A[0], a01 = A[1], a10 = A[2], a11 = A[3];
    const float c00 = C[0], c01 = C[1], c10 = C[2], c11 = C[3];
    const float d00 = D[0], d01 = D[1], d10 = D[2], d11 = D[3];

    const float dta00 = DTF * a00, dta01 = DTF * a01;
    const float dta10 = DTF * a10, dta11 = DTF * a11;
    const float dtc00 = DTF * c00, dtc01 = DTF * c01;
    const float dtc10 = DTF * c10, dtc11 = DTF * c11;

    // ---- riccati constants (SPECIAL: u=p00+d0, r=p01, v=p11+d1;
    //      X=[[u,r],[r,v]]; clip([-1,1]) provably inactive) ----
    const float KU1 = 1.0f + 2.0f * DTF * a00;
    const float KU2 = 2.0f * DTF * a01;
    const float KU3 = DTF * d00 * (1.0f - 2.0f * a00);
    const float KV1 = 1.0f + 2.0f * DTF * a11;
    const float KV2 = 2.0f * DTF * a10;
    const float KV3 = DTF * d11 * (1.0f - 2.0f * a11);
    const float KR1 = DTF * a10;
    const float KR2 = DTF * a01;
    const float KR3 = 1.0f + DTF * (a00 + a11);
    const float KR4 = -DTF * fmaf(a10, d00, a01 * d11);
    const ull K1p    = fpack(KU1, KV1);
    const ull K23p   = fpack(KU3, KV3);
    const ull K2p    = fpack(KU2, KV2);
    const ull KR12p  = fpack(KR1, KR2);
    const ull negdtp = fpack(-DTF, -DTF);
    // general-path constants (q-form)
    const float k00a = 1.0f + 2.0f * DTF * a00, k00b = 2.0f * DTF * a01;
    const float k00c = DTF * d00;
    const float k01a = DTF * a10, k01b = 1.0f + DTF * (a00 + a11);
    const float k01d = DTF * a01, k01c = DTF * d01;
    const float k11a = 1.0f + 2.0f * DTF * a11, k11b = 2.0f * DTF * a10;
    const float k11c = DTF * d11;

    // persistent per-warp state
    ull   uvp = fpack(1.0f + d00, 1.0f + d11);    // riccati (u,v)
    float rsc = 0.0f;                             // riccati r
    float p00 = 1.0f, p01 = 0.0f, p11 = 1.0f;     // riccati general
    float x0 = 1.0f, x1 = 0.0f;                   // scan state [1,0]

    // Prologue: prep warp pre-issues dy stages 0 and 1.
    if (wid == 2) {
        issue_dy_stage(dy, sm, 0, lane, b0);
        issue_dy_stage(dy, sm, 1, lane, b0);
    }

    for (int k = 0; k < NSTG + 3; ++k) {
        __syncthreads();

        if (wid == 3) {                     // ---------------- riccati: stage k
            if (k < NSTG && lane == 0) {
                const int slot = k & 1;
                if (SPECIAL) {
#pragma unroll 8
                    for (int i = 0; i < STG; ++i) {
                        sm->Xuv[slot][i] = uvp;                 // STS.64
                        sm->Xr[slot][i]  = rsc;                 // STS.32
                        const ull rp   = fpack(rsc, rsc);
                        const ull r2p  = mul2(rp, rp);
                        const ull sp   = fma2(negdtp, uvp, K1p);
                        const ull accp = fma2(K2p, rp, K23p);
                        const ull t12  = fma2(negdtp, rp, KR12p);
                        const ull inn  = fma2(sp, uvp, accp);
                        const ull nuv  = fma2(negdtp, r2p, inn);
                        float u, v, t1, t2;
                        funpack(u, v, uvp);
                        funpack(t1, t2, t12);
                        rsc = fmaf(t1, u, fmaf(t2, v, fmaf(KR3, rsc, KR4)));
                        uvp = nuv;
                    }
                } else {
#pragma unroll 2
                    for (int i = 0; i < STG; ++i) {
                        float x00 = fmaf(p00, c00, fmaf(p01, c01, d00));
                        float x01 = fmaf(p00, c10, fmaf(p01, c11, d10));
                        float x10 = fmaf(p01, c00, fmaf(p11, c01, d01));
                        float x11 = fmaf(p01, c10, fmaf(p11, c11, d11));
                        sm->Xuv[slot][i] = fpack(x00, x11);
                        sm->Xr[slot][i]  = x01;
                        sm->Xr2[slot][i] = x10;
                        float q00 = fmaf(k00a, p00, fmaf(k00b, p01, k00c));
                        float q01 = fmaf(k01a, p00, fmaf(k01b, p01, fmaf(k01d, p11, k01c)));
                        float q11 = fmaf(k11a, p11, fmaf(k11b, p01, k11c));
                        float m00 = fmaf(x00, x00, x01 * x01);
                        float m01 = fmaf(x00, x10, x01 * x11);
                        float m11 = fmaf(x10, x10, x11 * x11);
                        p00 = clamp1(fmaf(-DTF, m00, q00), -1.0f, 1.0f);
                        p01 = clamp1(fmaf(-DTF, m01, q01), -1.0f, 1.0f);
                        p11 = clamp1(fmaf(-DTF, m11, q11), -1.0f, 1.0f);
                    }
                }
            }
        } else if (wid == 2) {              // ---------------- prep: stage k-1
            const int s = k - 1;
            if (s >= 0 && s < NSTG) {
                // Keep the pending-group invariant: always commit a group.
                if (s + 2 < NSTG) {
                    issue_dy_stage(dy, sm, s + 2, lane, b0);
                } else {
                    asm volatile("cp.async.commit_group;" ::: "memory");
                }
                // Groups pending: {s, s+1, s+2} -> wait until only 2 remain.
                asm volatile("cp.async.wait_group 2;" ::: "memory");

                const int slot = s & 1;
                const int dslot = s % 3;
                float u, v;
                funpack(u, v, sm->Xuv[slot][lane]);   // my t = s*STG + lane
                const float r01 = sm->Xr[slot][lane];
                const float r10 = SPECIAL ? r01 : sm->Xr2[slot][lane];

                float4 Gv;                 // G' = I + dt(A - X C)
                if (SPECIAL) {
                    Gv = make_float4(1.0f + fmaf(-DTF, u,   dta00),
                                            fmaf(-DTF, r01, dta01),
                                            fmaf(-DTF, r01, dta10),
                                     1.0f + fmaf(-DTF, v,   dta11));
                } else {
                    Gv = make_float4(
                        1.0f + fmaf(-u,   dtc00, fmaf(-r01, dtc10, dta00)),
                               fmaf(-u,   dtc01, fmaf(-r01, dtc11, dta01)),
                               fmaf(-r10, dtc00, fmaf(-v,   dtc10, dta10)),
                        1.0f + fmaf(-r10, dtc01, fmaf(-v,   dtc11, dta11)));
                }
                sm->G[slot][lane] = Gv;

                // w = X dy, packed: (w0,w1) = (u,r10)*dx + (r01,v)*dyy
                const ull col0 = fpack(u, r10);
                const ull col1 = fpack(r01, v);
#pragma unroll 8
                for (int b = 0; b < 32; ++b) {
                    const float2 d = sm->dyraw[dslot][b][lane];   // LDS.64
                    const ull wp = fma2(col0, fpack(d.x, d.x),
                                        mul2(col1, fpack(d.y, d.y)));
                    *(ull*)&sm->w[slot][lane][b] = wp;            // STS.64
                }
            }
        } else if (wid == 0) {              // ---------------- scan: stage k-2
            const int s = k - 2;
            if (s >= 0 && s < NSTG) {
                const int slot = s & 1;
                float2 wr[LA]; float4 Gr[LA];
#pragma unroll
                for (int j = 0; j < LA; ++j) {
                    wr[j] = sm->w[slot][j][lane];
                    Gr[j] = sm->G[slot][j];
                }
#pragma unroll
                for (int i = 0; i < STG; ++i) {
                    const float2 wc = wr[i % LA];
                    const float4 Gc = Gr[i % LA];
                    if (i + LA < STG) {
                        wr[i % LA] = sm->w[slot][i + LA][lane];
                        Gr[i % LA] = sm->G[slot][i + LA];
                    }
                    sm->o[slot][i][lane] = make_float2(x0, x1);  // pre-update x
                    const float lo0 = x0 - CLIPX, hi0 = x0 + CLIPX;
                    const float lo1 = x1 - CLIPX, hi1 = x1 + CLIPX;
                    const float s0 = fmaf(Gc.x, x0, fmaf(Gc.y, x1, wc.x));
                    const float s1 = fmaf(Gc.z, x0, fmaf(Gc.w, x1, wc.y));
                    x0 = fminf(fmaxf(s0, lo0), hi0);
                    x1 = fminf(fmaxf(s1, lo1), hi1);
                }
            }
        } else {                            // ---------------- drain: stage k-3
            const int s = k - 3;
            if (s >= 0 && s < NSTG) {
                const int slot = s & 1;
                const int t0 = s * STG;
#pragma unroll 4
                for (int r = 0; r < 32; ++r) {
                    const float2 xv = sm->o[slot][lane][r];
                    float2 vv;
                    if (SPECIAL) {
                        vv = make_float2(DTF * xv.x, DTF * xv.y);
                    } else {
                        vv = make_float2(fmaf(dtc00, xv.x, dtc01 * xv.y),
                                         fmaf(dtc10, xv.x, dtc11 * xv.y));
                    }
                    outg[(size_t)(b0 + r) * T_STEPS + t0 + lane] = vv;
                }
            }
        }
    }
}

// ---------------------------------------------------------------------------
__global__ void __launch_bounds__(128, 1)
fused_kernel(const float* __restrict__ inputs,
             const float* __restrict__ A,
             const float* __restrict__ C,
             const float* __restrict__ D,
             float* __restrict__ out) {
    __shared__ Smem sm;
    const int wid  = threadIdx.x >> 5;
    const int lane = threadIdx.x & 31;
    const int b0   = blockIdx.x * 32;

    const bool special =
        (C[0] == 1.0f && C[1] == 0.0f && C[2] == 0.0f && C[3] == 1.0f &&
         D[1] == 0.0f && D[2] == 0.0f);

    const float2* dy = (const float2*)inputs;
    float2* o = (float2*)out;

    if (special) cta_run<true >(dy, A, C, D, o, &sm, wid, lane, b0);
    else         cta_run<false>(dy, A, C, D, o, &sm, wid, lane, b0);
}

// ---------------------------------------------------------------------------
extern "C" void kernel_launch(void* const* d_in, const int* in_sizes, int n_in,
                              void* d_out, int out_size) {
    const float* inputs = (const float*)d_in[0];   // [512, 8192, 2]
    const float* A      = (const float*)d_in[1];
    const float* C      = (const float*)d_in[2];
    const float* D      = (const float*)d_in[3];
    float*       out    = (float*)d_out;           // [512, 8192, 2]

    fused_kernel<<<NBATCH / 32, 128>>>(inputs, A, C, D, out);
}

// round 16
// speedup vs baseline: 2.1963x; 2.1963x over previous
#include <cuda_runtime.h>

// GRNN scan: B=512, T=8192, state dim 2.
//
// ONE kernel, 16 CTAs x 128 threads (4 warps, one per SMSP), 32 batches/CTA.
// Barrier-staged pipeline (stage = 32 steps), double-buffered smem by parity:
//   wid3 (riccati): lane0, batch-independent symmetric Riccati, (u,v) packed
//        f32x2 -> X ring.                                      [stage k]
//   wid2 (prep):    ALL 32 dy loads hoisted into registers (single batched
//        issue, one L2 round-trip), then w = X dy (packed) and
//        G' = I + dt(A - X C) into smem.                       [stage k-1]
//   wid0 (scan):    serial chain, pure smem, lookahead-4:
//        store x; s = G'x + w; x = min(max(s, x-.1), x+.1).    [stage k-2]
//   wid1 (drain):   out = dt C x -> gmem, coalesced.           [stage k-3]
// Runtime specialization for C == I, D diagonal (true here); general
// fallback kept.

#define T_STEPS 8192
#define NBATCH  512
#define DTF     1e-3f
#define CLIPX   0.1f
#define STG     32
#define NSTG    (T_STEPS / STG)
#define LA      4

typedef unsigned long long ull;

struct Smem {
    ull    Xuv[2][STG];        // riccati -> prep: packed (x00, x11)
    float  Xr[2][STG];         // riccati -> prep: x01 (== x10 special)
    float  Xr2[2][STG];        // general path only: x10
    float4 G[2][STG];          // prep -> scan: G' = I + dt(A - X C)
    float2 w[2][STG][33];      // prep -> scan, [t][b], padded
    float2 o[2][STG][33];      // scan -> drain, [t][b], padded
};

__device__ __forceinline__ float clamp1(float v, float lo, float hi) {
    return fminf(fmaxf(v, lo), hi);
}
__device__ __forceinline__ ull fpack(float lo, float hi) {
    ull d; asm("mov.b64 %0, {%1, %2};" : "=l"(d) : "f"(lo), "f"(hi)); return d;
}
__device__ __forceinline__ void funpack(float& lo, float& hi, ull v) {
    asm("mov.b64 {%0, %1}, %2;" : "=f"(lo), "=f"(hi) : "l"(v));
}
__device__ __forceinline__ ull fma2(ull a, ull b, ull c) {
    ull d; asm("fma.rn.f32x2 %0, %1, %2, %3;" : "=l"(d) : "l"(a), "l"(b), "l"(c));
    return d;
}
__device__ __forceinline__ ull mul2(ull a, ull b) {
    ull d; asm("mul.rn.f32x2 %0, %1, %2;" : "=l"(d) : "l"(a), "l"(b)); return d;
}

// ---------------------------------------------------------------------------
template <bool SPECIAL>
__device__ void cta_run(const float2* __restrict__ dy,
                        const float* __restrict__ A,
                        const float* __restrict__ C,
                        const float* __restrict__ D,
                        float2* __restrict__ outg,
                        Smem* sm, int wid, int lane, int b0) {
    const float a00 = A[0], a01 = A[1], a10 = A[2], a11 = A[3];
    const float c00 = C[0], c01 = C[1], c10 = C[2], c11 = C[3];
    const float d00 = D[0], d01 = D[1], d10 = D[2], d11 = D[3];

    const float dta00 = DTF * a00, dta01 = DTF * a01;
    const float dta10 = DTF * a10, dta11 = DTF * a11;
    const float dtc00 = DTF * c00, dtc01 = DTF * c01;
    const float dtc10 = DTF * c10, dtc11 = DTF * c11;

    // ---- riccati constants (SPECIAL: u=p00+d0, r=p01, v=p11+d1;
    //      X=[[u,r],[r,v]]; clip([-1,1]) provably inactive) ----
    const float KU1 = 1.0f + 2.0f * DTF * a00;
    const float KU2 = 2.0f * DTF * a01;
    const float KU3 = DTF * d00 * (1.0f - 2.0f * a00);
    const float KV1 = 1.0f + 2.0f * DTF * a11;
    const float KV2 = 2.0f * DTF * a10;
    const float KV3 = DTF * d11 * (1.0f - 2.0f * a11);
    const float KR1 = DTF * a10;
    const float KR2 = DTF * a01;
    const float KR3 = 1.0f + DTF * (a00 + a11);
    const float KR4 = -DTF * fmaf(a10, d00, a01 * d11);
    const ull K1p    = fpack(KU1, KV1);
    const ull K23p   = fpack(KU3, KV3);
    const ull K2p    = fpack(KU2, KV2);
    const ull KR12p  = fpack(KR1, KR2);
    const ull negdtp = fpack(-DTF, -DTF);
    // general-path constants (q-form)
    const float k00a = 1.0f + 2.0f * DTF * a00, k00b = 2.0f * DTF * a01;
    const float k00c = DTF * d00;
    const float k01a = DTF * a10, k01b = 1.0f + DTF * (a00 + a11);
    const float k01d = DTF * a01, k01c = DTF * d01;
    const float k11a = 1.0f + 2.0f * DTF * a11, k11b = 2.0f * DTF * a10;
    const float k11c = DTF * d11;

    // persistent per-warp state
    ull   uvp = fpack(1.0f + d00, 1.0f + d11);    // riccati (u,v)
    float rsc = 0.0f;                             // riccati r
    float p00 = 1.0f, p01 = 0.0f, p11 = 1.0f;     // riccati general
    float x0 = 1.0f, x1 = 0.0f;                   // scan state [1,0]

    for (int k = 0; k < NSTG + 3; ++k) {
        __syncthreads();

        if (wid == 3) {                     // ---------------- riccati: stage k
            if (k < NSTG && lane == 0) {
                const int slot = k & 1;
                if (SPECIAL) {
#pragma unroll 8
                    for (int i = 0; i < STG; ++i) {
                        sm->Xuv[slot][i] = uvp;                 // STS.64
                        sm->Xr[slot][i]  = rsc;                 // STS.32
                        const ull rp   = fpack(rsc, rsc);
                        const ull r2p  = mul2(rp, rp);
                        const ull sp   = fma2(negdtp, uvp, K1p);
                        const ull accp = fma2(K2p, rp, K23p);
                        const ull t12  = fma2(negdtp, rp, KR12p);
                        const ull inn  = fma2(sp, uvp, accp);
                        const ull nuv  = fma2(negdtp, r2p, inn);
                        float u, v, t1, t2;
                        funpack(u, v, uvp);
                        funpack(t1, t2, t12);
                        rsc = fmaf(t1, u, fmaf(t2, v, fmaf(KR3, rsc, KR4)));
                        uvp = nuv;
                    }
                } else {
#pragma unroll 2
                    for (int i = 0; i < STG; ++i) {
                        float x00 = fmaf(p00, c00, fmaf(p01, c01, d00));
                        float x01 = fmaf(p00, c10, fmaf(p01, c11, d10));
                        float x10 = fmaf(p01, c00, fmaf(p11, c01, d01));
                        float x11 = fmaf(p01, c10, fmaf(p11, c11, d11));
                        sm->Xuv[slot][i] = fpack(x00, x11);
                        sm->Xr[slot][i]  = x01;
                        sm->Xr2[slot][i] = x10;
                        float q00 = fmaf(k00a, p00, fmaf(k00b, p01, k00c));
                        float q01 = fmaf(k01a, p00, fmaf(k01b, p01, fmaf(k01d, p11, k01c)));
                        float q11 = fmaf(k11a, p11, fmaf(k11b, p01, k11c));
                        float m00 = fmaf(x00, x00, x01 * x01);
                        float m01 = fmaf(x00, x10, x01 * x11);
                        float m11 = fmaf(x10, x10, x11 * x11);
                        p00 = clamp1(fmaf(-DTF, m00, q00), -1.0f, 1.0f);
                        p01 = clamp1(fmaf(-DTF, m01, q01), -1.0f, 1.0f);
                        p11 = clamp1(fmaf(-DTF, m11, q11), -1.0f, 1.0f);
                    }
                }
            }
        } else if (wid == 2) {              // ---------------- prep: stage k-1
            const int s = k - 1;
            if (s >= 0 && s < NSTG) {
                const int slot = s & 1;
                float u, v;
                funpack(u, v, sm->Xuv[slot][lane]);   // my t = s*STG + lane
                const float r01 = sm->Xr[slot][lane];
                const float r10 = SPECIAL ? r01 : sm->Xr2[slot][lane];

                // ALL 32 dy loads issued before any consumption: one L2
                // round-trip per stage instead of two.
                const size_t tb = (size_t)s * STG + lane;
                float2 dbuf[32];
#pragma unroll
                for (int j = 0; j < 32; ++j)
                    dbuf[j] = __ldg(&dy[(size_t)(b0 + j) * T_STEPS + tb]);

                float4 Gv;                 // G' = I + dt(A - X C)
                if (SPECIAL) {
                    Gv = make_float4(1.0f + fmaf(-DTF, u,   dta00),
                                            fmaf(-DTF, r01, dta01),
                                            fmaf(-DTF, r01, dta10),
                                     1.0f + fmaf(-DTF, v,   dta11));
                } else {
                    Gv = make_float4(
                        1.0f + fmaf(-u,   dtc00, fmaf(-r01, dtc10, dta00)),
                               fmaf(-u,   dtc01, fmaf(-r01, dtc11, dta01)),
                               fmaf(-r10, dtc00, fmaf(-v,   dtc10, dta10)),
                        1.0f + fmaf(-r10, dtc01, fmaf(-v,   dtc11, dta11)));
                }
                sm->G[slot][lane] = Gv;

                // w = X dy, packed: (w0,w1) = (u,r10)*dx + (r01,v)*dyy
                const ull col0 = fpack(u, r10);
                const ull col1 = fpack(r01, v);
#pragma unroll
                for (int j = 0; j < 32; ++j) {
                    const ull wp = fma2(col0, fpack(dbuf[j].x, dbuf[j].x),
                                        mul2(col1, fpack(dbuf[j].y, dbuf[j].y)));
                    *(ull*)&sm->w[slot][lane][j] = wp;           // STS.64
                }
            }
        } else if (wid == 0) {              // ---------------- scan: stage k-2
            const int s = k - 2;
            if (s >= 0 && s < NSTG) {
                const int slot = s & 1;
                float2 wr[LA]; float4 Gr[LA];
#pragma unroll
                for (int j = 0; j < LA; ++j) {
                    wr[j] = sm->w[slot][j][lane];
                    Gr[j] = sm->G[slot][j];
                }
#pragma unroll
                for (int i = 0; i < STG; ++i) {
                    const float2 wc = wr[i % LA];
                    const float4 Gc = Gr[i % LA];
                    if (i + LA < STG) {
                        wr[i % LA] = sm->w[slot][i + LA][lane];
                        Gr[i % LA] = sm->G[slot][i + LA];
                    }
                    sm->o[slot][i][lane] = make_float2(x0, x1);  // pre-update x
                    const float lo0 = x0 - CLIPX, hi0 = x0 + CLIPX;
                    const float lo1 = x1 - CLIPX, hi1 = x1 + CLIPX;
                    const float s0 = fmaf(Gc.x, x0, fmaf(Gc.y, x1, wc.x));
                    const float s1 = fmaf(Gc.z, x0, fmaf(Gc.w, x1, wc.y));
                    x0 = fminf(fmaxf(s0, lo0), hi0);
                    x1 = fminf(fmaxf(s1, lo1), hi1);
                }
            }
        } else {                            // ---------------- drain: stage k-3
            const int s = k - 3;
            if (s >= 0 && s < NSTG) {
                const int slot = s & 1;
                const int t0 = s * STG;
#pragma unroll 4
                for (int r = 0; r < 32; ++r) {
                    const float2 xv = sm->o[slot][lane][r];
                    float2 vv;
                    if (SPECIAL) {
                        vv = make_float2(DTF * xv.x, DTF * xv.y);
                    } else {
                        vv = make_float2(fmaf(dtc00, xv.x, dtc01 * xv.y),
                                         fmaf(dtc10, xv.x, dtc11 * xv.y));
                    }
                    outg[(size_t)(b0 + r) * T_STEPS + t0 + lane] = vv;
                }
            }
        }
    }
}

// ---------------------------------------------------------------------------
__global__ void __launch_bounds__(128, 1)
fused_kernel(const float* __restrict__ inputs,
             const float* __restrict__ A,
             const float* __restrict__ C,
             const float* __restrict__ D,
             float* __restrict__ out) {
    __shared__ Smem sm;
    const int wid  = threadIdx.x >> 5;
    const int lane = threadIdx.x & 31;
    const int b0   = blockIdx.x * 32;

    const bool special =
        (C[0] == 1.0f && C[1] == 0.0f && C[2] == 0.0f && C[3] == 1.0f &&
         D[1] == 0.0f && D[2] == 0.0f);

    const float2* dy = (const float2*)inputs;
    float2* o = (float2*)out;

    if (special) cta_run<true >(dy, A, C, D, o, &sm, wid, lane, b0);
    else         cta_run<false>(dy, A, C, D, o, &sm, wid, lane, b0);
}

// ---------------------------------------------------------------------------
extern "C" void kernel_launch(void* const* d_in, const int* in_sizes, int n_in,
                              void* d_out, int out_size) {
    const float* inputs = (const float*)d_in[0];   // [512, 8192, 2]
    const float* A      = (const float*)d_in[1];
    const float* C      = (const float*)d_in[2];
    const float* D      = (const float*)d_in[3];
    float*       out    = (float*)d_out;           // [512, 8192, 2]

    fused_kernel<<<NBATCH / 32, 128>>>(inputs, A, C, D, out);
}

// round 17
// speedup vs baseline: 2.3094x; 1.0515x over previous
#include <cuda_runtime.h>

// GRNN scan: B=512, T=8192, state dim 2.
//
// ONE kernel, 16 CTAs x 128 threads (4 warps, one per SMSP), 32 batches/CTA.
// Barrier-staged pipeline, stage = 64 steps (128 stages), double-buffered
// dynamic smem (~72KB). Each warp runs its OWN loop with one __syncthreads
// per stage (same barrier count in all warps) so role dispatch happens once:
//   wid3 (riccati): lane0, batch-independent symmetric Riccati, (u,v) packed
//        f32x2 -> X ring.                                      [stage k]
//   wid2 (prep):    dy loads hoisted into registers (2 x 32-load batches),
//        w = X dy (packed), G' = I + dt(A - X C).              [stage k-1]
//   wid0 (scan):    serial chain, pure smem, lookahead-4:
//        store x; s = G'x + w; x = min(max(s, x-.1), x+.1).    [stage k-2]
//   wid1 (drain):   out = dt C x -> gmem, coalesced.           [stage k-3]
// Runtime specialization for C == I, D diagonal (true here); general
// fallback kept.

#define T_STEPS 8192
#define NBATCH  512
#define DTF     1e-3f
#define CLIPX   0.1f
#define STG     64
#define NSTG    (T_STEPS / STG)
#define LA      4

typedef unsigned long long ull;

struct Smem {
    ull    Xuv[2][STG];        // riccati -> prep: packed (x00, x11)
    float  Xr[2][STG];         // riccati -> prep: x01 (== x10 special)
    float  Xr2[2][STG];        // general path only: x10
    float4 G[2][STG];          // prep -> scan: G' = I + dt(A - X C)
    float2 w[2][STG][33];      // prep -> scan, [t][b], padded
    float2 o[2][STG][33];      // scan -> drain, [t][b], padded
};

__device__ __forceinline__ float clamp1(float v, float lo, float hi) {
    return fminf(fmaxf(v, lo), hi);
}
__device__ __forceinline__ ull fpack(float lo, float hi) {
    ull d; asm("mov.b64 %0, {%1, %2};" : "=l"(d) : "f"(lo), "f"(hi)); return d;
}
__device__ __forceinline__ void funpack(float& lo, float& hi, ull v) {
    asm("mov.b64 {%0, %1}, %2;" : "=f"(lo), "=f"(hi) : "l"(v));
}
__device__ __forceinline__ ull fma2(ull a, ull b, ull c) {
    ull d; asm("fma.rn.f32x2 %0, %1, %2, %3;" : "=l"(d) : "l"(a), "l"(b), "l"(c));
    return d;
}
__device__ __forceinline__ ull mul2(ull a, ull b) {
    ull d; asm("mul.rn.f32x2 %0, %1, %2;" : "=l"(d) : "l"(a), "l"(b)); return d;
}

// ---------------------------------------------------------------------------
template <bool SPECIAL>
__device__ void cta_run(const float2* __restrict__ dy,
                        const float* __restrict__ A,
                        const float* __restrict__ C,
                        const float* __restrict__ D,
                        float2* __restrict__ outg,
                        Smem* sm, int wid, int lane, int b0) {
    const float a00 = A[0], a01 = A[1], a10 = A[2], a11 = A[3];
    const float c00 = C[0], c01 = C[1], c10 = C[2], c11 = C[3];
    const float d00 = D[0], d01 = D[1], d10 = D[2], d11 = D[3];

    const float dta00 = DTF * a00, dta01 = DTF * a01;
    const float dta10 = DTF * a10, dta11 = DTF * a11;
    const float dtc00 = DTF * c00, dtc01 = DTF * c01;
    const float dtc10 = DTF * c10, dtc11 = DTF * c11;

    if (wid == 3) {
        // ------------------ riccati: stage k -------------------------------
        // SPECIAL: u=p00+d0, r=p01, v=p11+d1; X=[[u,r],[r,v]];
        // clip([-1,1]) provably inactive (monotone decay from I).
        const float KU1 = 1.0f + 2.0f * DTF * a00;
        const float KU2 = 2.0f * DTF * a01;
        const float KU3 = DTF * d00 * (1.0f - 2.0f * a00);
        const float KV1 = 1.0f + 2.0f * DTF * a11;
        const float KV2 = 2.0f * DTF * a10;
        const float KV3 = DTF * d11 * (1.0f - 2.0f * a11);
        const float KR1 = DTF * a10;
        const float KR2 = DTF * a01;
        const float KR3 = 1.0f + DTF * (a00 + a11);
        const float KR4 = -DTF * fmaf(a10, d00, a01 * d11);
        const ull K1p    = fpack(KU1, KV1);
        const ull K23p   = fpack(KU3, KV3);
        const ull K2p    = fpack(KU2, KV2);
        const ull KR12p  = fpack(KR1, KR2);
        const ull negdtp = fpack(-DTF, -DTF);
        // general-path constants (q-form)
        const float k00a = 1.0f + 2.0f * DTF * a00, k00b = 2.0f * DTF * a01;
        const float k00c = DTF * d00;
        const float k01a = DTF * a10, k01b = 1.0f + DTF * (a00 + a11);
        const float k01d = DTF * a01, k01c = DTF * d01;
        const float k11a = 1.0f + 2.0f * DTF * a11, k11b = 2.0f * DTF * a10;
        const float k11c = DTF * d11;

        ull   uvp = fpack(1.0f + d00, 1.0f + d11);
        float rsc = 0.0f;
        float p00 = 1.0f, p01 = 0.0f, p11 = 1.0f;

        for (int k = 0; k < NSTG + 3; ++k) {
            __syncthreads();
            if (k < NSTG && lane == 0) {
                const int slot = k & 1;
                if (SPECIAL) {
#pragma unroll 8
                    for (int i = 0; i < STG; ++i) {
                        sm->Xuv[slot][i] = uvp;                 // STS.64
                        sm->Xr[slot][i]  = rsc;                 // STS.32
                        const ull rp   = fpack(rsc, rsc);
                        const ull r2p  = mul2(rp, rp);
                        const ull sp   = fma2(negdtp, uvp, K1p);
                        const ull accp = fma2(K2p, rp, K23p);
                        const ull t12  = fma2(negdtp, rp, KR12p);
                        const ull inn  = fma2(sp, uvp, accp);
                        const ull nuv  = fma2(negdtp, r2p, inn);
                        float u, v, t1, t2;
                        funpack(u, v, uvp);
                        funpack(t1, t2, t12);
                        rsc = fmaf(t1, u, fmaf(t2, v, fmaf(KR3, rsc, KR4)));
                        uvp = nuv;
                    }
                } else {
#pragma unroll 2
                    for (int i = 0; i < STG; ++i) {
                        float x00 = fmaf(p00, c00, fmaf(p01, c01, d00));
                        float x01 = fmaf(p00, c10, fmaf(p01, c11, d10));
                        float x10 = fmaf(p01, c00, fmaf(p11, c01, d01));
                        float x11 = fmaf(p01, c10, fmaf(p11, c11, d11));
                        sm->Xuv[slot][i] = fpack(x00, x11);
                        sm->Xr[slot][i]  = x01;
                        sm->Xr2[slot][i] = x10;
                        float q00 = fmaf(k00a, p00, fmaf(k00b, p01, k00c));
                        float q01 = fmaf(k01a, p00, fmaf(k01b, p01, fmaf(k01d, p11, k01c)));
                        float q11 = fmaf(k11a, p11, fmaf(k11b, p01, k11c));
                        float m00 = fmaf(x00, x00, x01 * x01);
                        float m01 = fmaf(x00, x10, x01 * x11);
                        float m11 = fmaf(x10, x10, x11 * x11);
                        p00 = clamp1(fmaf(-DTF, m00, q00), -1.0f, 1.0f);
                        p01 = clamp1(fmaf(-DTF, m01, q01), -1.0f, 1.0f);
                        p11 = clamp1(fmaf(-DTF, m11, q11), -1.0f, 1.0f);
                    }
                }
            }
        }
    } else if (wid == 2) {
        // ------------------ prep: stage k-1 --------------------------------
        for (int k = 0; k < NSTG + 3; ++k) {
            __syncthreads();
            const int s = k - 1;
            if (s >= 0 && s < NSTG) {
                const int slot = s & 1;
#pragma unroll
                for (int h = 0; h < 2; ++h) {
                    const int t = lane + 32 * h;
                    float u, v;
                    funpack(u, v, sm->Xuv[slot][t]);
                    const float r01 = sm->Xr[slot][t];
                    const float r10 = SPECIAL ? r01 : sm->Xr2[slot][t];

                    // 32 dy loads hoisted before consumption (one round trip)
                    const size_t tb = (size_t)s * STG + t;
                    float2 dbuf[32];
#pragma unroll
                    for (int j = 0; j < 32; ++j)
                        dbuf[j] = __ldg(&dy[(size_t)(b0 + j) * T_STEPS + tb]);

                    float4 Gv;                 // G' = I + dt(A - X C)
                    if (SPECIAL) {
                        Gv = make_float4(1.0f + fmaf(-DTF, u,   dta00),
                                                fmaf(-DTF, r01, dta01),
                                                fmaf(-DTF, r01, dta10),
                                         1.0f + fmaf(-DTF, v,   dta11));
                    } else {
                        Gv = make_float4(
                            1.0f + fmaf(-u,   dtc00, fmaf(-r01, dtc10, dta00)),
                                   fmaf(-u,   dtc01, fmaf(-r01, dtc11, dta01)),
                                   fmaf(-r10, dtc00, fmaf(-v,   dtc10, dta10)),
                            1.0f + fmaf(-r10, dtc01, fmaf(-v,   dtc11, dta11)));
                    }
                    sm->G[slot][t] = Gv;

                    // w = X dy, packed: (w0,w1) = (u,r10)*dx + (r01,v)*dyy
                    const ull col0 = fpack(u, r10);
                    const ull col1 = fpack(r01, v);
#pragma unroll
                    for (int j = 0; j < 32; ++j) {
                        const ull wp = fma2(col0, fpack(dbuf[j].x, dbuf[j].x),
                                            mul2(col1, fpack(dbuf[j].y, dbuf[j].y)));
                        *(ull*)&sm->w[slot][t][j] = wp;          // STS.64
                    }
                }
            }
        }
    } else if (wid == 0) {
        // ------------------ scan: stage k-2 --------------------------------
        float x0 = 1.0f, x1 = 0.0f;                   // x0 = [1, 0]
        for (int k = 0; k < NSTG + 3; ++k) {
            __syncthreads();
            const int s = k - 2;
            if (s >= 0 && s < NSTG) {
                const int slot = s & 1;
                float2 wr[LA]; float4 Gr[LA];
#pragma unroll
                for (int j = 0; j < LA; ++j) {
                    wr[j] = sm->w[slot][j][lane];
                    Gr[j] = sm->G[slot][j];
                }
#pragma unroll
                for (int i = 0; i < STG; ++i) {
                    const float2 wc = wr[i % LA];
                    const float4 Gc = Gr[i % LA];
                    if (i + LA < STG) {
                        wr[i % LA] = sm->w[slot][i + LA][lane];
                        Gr[i % LA] = sm->G[slot][i + LA];
                    }
                    sm->o[slot][i][lane] = make_float2(x0, x1);  // pre-update x
                    const float lo0 = x0 - CLIPX, hi0 = x0 + CLIPX;
                    const float lo1 = x1 - CLIPX, hi1 = x1 + CLIPX;
                    const float s0 = fmaf(Gc.x, x0, fmaf(Gc.y, x1, wc.x));
                    const float s1 = fmaf(Gc.z, x0, fmaf(Gc.w, x1, wc.y));
                    x0 = fminf(fmaxf(s0, lo0), hi0);
                    x1 = fminf(fmaxf(s1, lo1), hi1);
                }
            }
        }
    } else {
        // ------------------ drain: stage k-3 -------------------------------
        for (int k = 0; k < NSTG + 3; ++k) {
            __syncthreads();
            const int s = k - 3;
            if (s >= 0 && s < NSTG) {
                const int slot = s & 1;
                const int t0 = s * STG;
#pragma unroll 4
                for (int r = 0; r < 32; ++r) {
#pragma unroll
                    for (int h = 0; h < 2; ++h) {
                        const int t = lane + 32 * h;
                        const float2 xv = sm->o[slot][t][r];
                        float2 vv;
                        if (SPECIAL) {
                            vv = make_float2(DTF * xv.x, DTF * xv.y);
                        } else {
                            vv = make_float2(fmaf(dtc00, xv.x, dtc01 * xv.y),
                                             fmaf(dtc10, xv.x, dtc11 * xv.y));
                        }
                        outg[(size_t)(b0 + r) * T_STEPS + t0 + t] = vv;
                    }
                }
            }
        }
    }
}

// ---------------------------------------------------------------------------
__global__ void __launch_bounds__(128, 1)
fused_kernel(const float* __restrict__ inputs,
             const float* __restrict__ A,
             const float* __restrict__ C,
             const float* __restrict__ D,
             float* __restrict__ out) {
    extern __shared__ char smraw[];
    Smem* sm = (Smem*)smraw;
    const int wid  = threadIdx.x >> 5;
    const int lane = threadIdx.x & 31;
    const int b0   = blockIdx.x * 32;

    const bool special =
        (C[0] == 1.0f && C[1] == 0.0f && C[2] == 0.0f && C[3] == 1.0f &&
         D[1] == 0.0f && D[2] == 0.0f);

    const float2* dy = (const float2*)inputs;
    float2* o = (float2*)out;

    if (special) cta_run<true >(dy, A, C, D, o, sm, wid, lane, b0);
    else         cta_run<false>(dy, A, C, D, o, sm, wid, lane, b0);
}

// ---------------------------------------------------------------------------
extern "C" void kernel_launch(void* const* d_in, const int* in_sizes, int n_in,
                              void* d_out, int out_size) {
    const float* inputs = (const float*)d_in[0];   // [512, 8192, 2]
    const float* A      = (const float*)d_in[1];
    const float* C      = (const float*)d_in[2];
    const float* D      = (const float*)d_in[3];
    float*       out    = (float*)d_out;           // [512, 8192, 2]

    cudaFuncSetAttribute(fused_kernel,
                         cudaFuncAttributeMaxDynamicSharedMemorySize,
                         (int)sizeof(Smem));
    fused_kernel<<<NBATCH / 32, 128, sizeof(Smem)>>>(inputs, A, C, D, out);
}